// round 3
// baseline (speedup 1.0000x reference)
#include <cuda_runtime.h>
#include <cstdint>

#define NN 2048
#define TT 4096
#define MAXS 256
#define G_CTAS 64
#define DT 2.44140625e-4f   /* (1-0)/4096, exact in fp32 */
#define ALPHA_F 0.01f

// Per-step sync word: low 32 bits = min spiking neuron index (init 0x7FFFFFFF),
// high 32 bits = number of CTAs that have published this step.
__device__ unsigned long long g_sync[TT];

__global__ void init_kernel(float* __restrict__ out) {
    int idx = blockIdx.x * blockDim.x + threadIdx.x;
    int stride = gridDim.x * blockDim.x;
    for (int k = idx; k < TT; k += stride) g_sync[k] = 0x7FFFFFFFull;

    // Output layout: [ys (T*N*3)] [tev (256)] [yev (256*N*3)] [et (256*N)] [num_spikes (1)]
    float* tev = out + (size_t)TT * NN * 3;
    const int inf_n = MAXS + MAXS * NN * 3;          // tevents + yevents -> +inf
    const float finf = __int_as_float(0x7f800000);
    for (int t = idx; t < inf_n; t += stride) tev[t] = finf;
    float* et = tev + inf_n;
    const int et_n = MAXS * NN;                      // event_types -> 0
    for (int t = idx; t < et_n; t += stride) et[t] = 0.0f;
}

__device__ __forceinline__ unsigned long long ld_vol_u64(const unsigned long long* p) {
    unsigned long long v;
    asm volatile("ld.volatile.global.u64 %0, [%1];" : "=l"(v) : "l"(p));
    return v;
}

// Exact jax.nn.softplus(x) = logaddexp(x, 0) = max(x,0) + log1p(exp(-|x|))
__device__ __forceinline__ float softplus_ref(float v) {
    float ax = fabsf(v);
    float e  = expf(-ax);        // libdevice __nv_expf (matches XLA GPU)
    float l  = log1pf(e);        // libdevice __nv_log1pf
    return __fadd_rn(fmaxf(v, 0.0f), l);
}

__global__ void __launch_bounds__(32, 1)
sim_kernel(const float* __restrict__ w,  const float* __restrict__ mu,
           const float* __restrict__ v0, const float* __restrict__ i0,
           const float* __restrict__ ic, const float* __restrict__ u0,
           const float* __restrict__ ur, float* __restrict__ out)
{
    const int lane = threadIdx.x;
    const int cta  = blockIdx.x;
    const int n    = cta * 32 + lane;

    const float mu1  = mu[0];
    const float nmu2 = -mu[1];
    const float dt   = DT;

    float* ys  = out;
    float* tev = out + (size_t)TT * NN * 3;
    float* yev = tev + MAXS;
    float* et  = yev + (size_t)MAXS * NN * 3;
    float* nsp = et  + (size_t)MAXS * NN;

    // Carried state (end of step k-1):
    float v   = v0[n];                              // v2(k-1), resolved
    float s   = __fsub_rn(logf(u0[n]), ALPHA_F);    // s2(k-1), resolved
    float i1c = 0.0f;                               // i1(k-1) = decayed i, BEFORE w-row (k>=1)
    const float i0v = i0[n];
    float v1s = 0.0f, s1s = 0.0f;                   // saved v1(k-1), s1(k-1) for yevents
    bool  maskp = false;                            // mask(k-1) for event_types
    int   cnt = 0;

    unsigned long long* syncp = g_sync;

    for (int k = 0; k <= TT; ++k) {
        float ick = 0.0f, uk = 0.0f, s1 = 0.0f;
        bool  mask = false;

        if (k < TT) {
            // Inputs for step k (issued early, consumed after the resolve)
            ick = __ldg(&ic[(size_t)k * NN + n]);
            uk  = __ldg(&ur[(size_t)k * NN + n]);

            // ---- publish step k (depends only on v2(k-1), s2(k-1): no w-row needed) ----
            float sp = softplus_ref(v);
            s1   = __fadd_rn(s, __fmul_rn(dt, sp));
            mask = (s1 >= 0.0f);
            unsigned bal = __ballot_sync(0xffffffffu, mask);
            if (lane == 0) {
                if (bal) atomicMin((int*)(syncp + k), cta * 32 + (__ffs(bal) - 1));
                __threadfence();
                atomicAdd(((unsigned int*)(syncp + k)) + 1, 1u);
            }
        }

        // ---- resolve step k-1 (2-step slack: publish(k-1) happened one full iter ago) ----
        float i2km1;
        if (k == 0) {
            i2km1 = i0v;
        } else {
            unsigned long long x = 0;
            if (lane == 0) {
                do { x = ld_vol_u64(syncp + (k - 1)); }
                while ((unsigned)(x >> 32) != (unsigned)G_CTAS);
            }
            int e = (int)__shfl_sync(0xffffffffu, (unsigned)x, 0);
            bool eventp = (e < NN);
            float wv = eventp ? __ldg(&w[(size_t)e * NN + n]) : 0.0f;
            i2km1 = __fadd_rn(i1c, wv);   // i1 + 0 is exact when no event

            // deferred outputs for step k-1: y_new == [v2, i2, s2] in all cases
            size_t ob = ((size_t)(k - 1) * NN + n) * 3;
            ys[ob + 0] = v;
            ys[ob + 1] = i2km1;
            ys[ob + 2] = s;
            if (eventp && cnt < MAXS) {
                size_t eb = ((size_t)cnt * NN + n) * 3;
                yev[eb + 0] = v1s;   // pre-transition y at event step
                yev[eb + 1] = i1c;
                yev[eb + 2] = s1s;
                et[(size_t)cnt * NN + n] = maskp ? 1.0f : 0.0f;
                if (n == 0) tev[cnt] = __fmul_rn((float)k, dt);  // ((k-1)+1)*dt
                cnt++;
            }
        }

        if (k < TT) {
            // ---- advance to end-of-step-k state ----
            float t1  = __fsub_rn(__fadd_rn(i2km1, ick), v);          // (i + ic) - v
            float v1  = __fadd_rn(v, __fmul_rn(dt, __fmul_rn(mu1, t1)));
            float i1n = __fadd_rn(i2km1, __fmul_rn(dt, __fmul_rn(nmu2, i2km1)));
            float v2  = mask ? __fsub_rn(v1, 1.0f) : v1;
            float s2  = mask ? __fsub_rn(logf(uk), ALPHA_F) : s1;

            v1s = v1; s1s = s1; maskp = mask;
            v = v2; i1c = i1n; s = s2;
        }
    }

    if (n == 0) nsp[0] = (float)cnt;
}

extern "C" void kernel_launch(void* const* d_in, const int* in_sizes, int n_in,
                              void* d_out, int out_size) {
    const float* w  = (const float*)d_in[0];
    const float* mu = (const float*)d_in[1];
    const float* v0 = (const float*)d_in[2];
    const float* i0 = (const float*)d_in[3];
    const float* ic = (const float*)d_in[4];
    const float* u0 = (const float*)d_in[5];
    const float* ur = (const float*)d_in[6];
    float* out = (float*)d_out;

    init_kernel<<<512, 256>>>(out);
    sim_kernel<<<G_CTAS, 32>>>(w, mu, v0, i0, ic, u0, ur, out);
    (void)in_sizes; (void)n_in; (void)out_size;
}

// round 5
// speedup vs baseline: 2.1601x; 2.1601x over previous
#include <cuda_runtime.h>
#include <cstdint>

#define NN 2048
#define TT 4096
#define MAXS 256
#define G_CTAS 64
#define DT 2.44140625e-4f   /* (1-0)/4096, exact in fp32 */
#define ALPHA_F 0.01f

// Per-step, per-CTA publish slot.
// 0 = not yet arrived; otherwise: (min spiking neuron index + 1), or 0x7FFFFFFF
// if this CTA had no spike. The value IS the message -> no fence, no atomics.
__device__ unsigned g_slot[TT * G_CTAS];

__global__ void init_kernel(float* __restrict__ out) {
    int idx = blockIdx.x * blockDim.x + threadIdx.x;
    int stride = gridDim.x * blockDim.x;
    for (int k = idx; k < TT * G_CTAS; k += stride) g_slot[k] = 0u;

    // Output layout: [ys (T*N*3)] [tev (256)] [yev (256*N*3)] [et (256*N)] [num_spikes (1)]
    float* tev = out + (size_t)TT * NN * 3;
    const int inf_n = MAXS + MAXS * NN * 3;          // tevents + yevents -> +inf
    const float finf = __int_as_float(0x7f800000);
    for (int t = idx; t < inf_n; t += stride) tev[t] = finf;
    float* et = tev + inf_n;
    const int et_n = MAXS * NN;                      // event_types -> 0
    for (int t = idx; t < et_n; t += stride) et[t] = 0.0f;
}

__device__ __forceinline__ unsigned ld_vol_u32(const unsigned* p) {
    unsigned v;
    asm volatile("ld.volatile.global.u32 %0, [%1];" : "=r"(v) : "l"(p));
    return v;
}
__device__ __forceinline__ void st_vol_u32(unsigned* p, unsigned v) {
    asm volatile("st.volatile.global.u32 [%0], %1;" :: "l"(p), "r"(v) : "memory");
}

// Exact jax.nn.softplus(x) = max(x,0) + log1p(exp(-|x|))
__device__ __forceinline__ float softplus_ref(float v) {
    float ax = fabsf(v);
    float e  = expf(-ax);        // libdevice expf (matches XLA GPU lowering)
    float l  = log1pf(e);        // libdevice log1pf
    return __fadd_rn(fmaxf(v, 0.0f), l);
}

__global__ void __launch_bounds__(32, 1)
sim_kernel(const float* __restrict__ w,  const float* __restrict__ mu,
           const float* __restrict__ v0, const float* __restrict__ i0,
           const float* __restrict__ ic, const float* __restrict__ u0,
           const float* __restrict__ ur, float* __restrict__ out)
{
    const int lane = threadIdx.x;
    const int cta  = blockIdx.x;
    const int n    = cta * 32 + lane;

    const float mu1  = mu[0];
    const float nmu2 = -mu[1];
    const float dt   = DT;

    float* ys  = out;
    float* tev = out + (size_t)TT * NN * 3;
    float* yev = tev + MAXS;
    float* et  = yev + (size_t)MAXS * NN * 3;
    float* nsp = et  + (size_t)MAXS * NN;

    // Carried state (end of step k-1):
    float v   = v0[n];                              // v2(k-1), resolved
    float s   = __fsub_rn(logf(u0[n]), ALPHA_F);    // s2(k-1), resolved
    float i1c = 0.0f;                               // i1(k-1) = decayed i, BEFORE w-row (k>=1)
    const float i0v = i0[n];
    float v1s = 0.0f, s1s = 0.0f;                   // saved v1(k-1), s1(k-1) for yevents
    bool  maskp = false;                            // mask(k-1) for event_types
    int   cnt = 0;

    for (int k = 0; k <= TT; ++k) {
        float ick = 0.0f, uk = 0.0f, s1 = 0.0f;
        bool  mask = false;

        if (k < TT) {
            // Inputs for step k (issued early; latency hidden under the poll)
            ick = __ldg(&ic[(size_t)k * NN + n]);
            uk  = __ldg(&ur[(size_t)k * NN + n]);

            // ---- publish step k (needs only v2(k-1), s2(k-1); no w-row) ----
            float sp = softplus_ref(v);
            s1   = __fadd_rn(s, __fmul_rn(dt, sp));
            mask = (s1 >= 0.0f);
            unsigned bal = __ballot_sync(0xffffffffu, mask);
            // __ffs is 1-based -> cta*32 + ffs == (first spiking index) + 1
            unsigned val = bal ? (unsigned)(cta * 32) + (unsigned)__ffs(bal)
                               : 0x7FFFFFFFu;
            if (lane == 0) st_vol_u32(&g_slot[(size_t)k * G_CTAS + cta], val);
        }

        // ---- resolve step k-1 (published one full iteration ago: 2-step slack) ----
        float i2km1;
        if (k == 0) {
            i2km1 = i0v;
        } else {
            const unsigned* base = g_slot + (size_t)(k - 1) * G_CTAS;
            unsigned a, b;
            do {
                a = ld_vol_u32(base + lane);
                b = ld_vol_u32(base + lane + 32);
            } while (__ballot_sync(0xffffffffu, umin(a, b) == 0u));
            unsigned m = __reduce_min_sync(0xffffffffu, umin(a, b));
            int e = (int)m - 1;                   // global argmax(mask) if any
            bool eventp = (e < NN);
            float wv = eventp ? __ldg(&w[(size_t)e * NN + n]) : 0.0f;
            i2km1 = __fadd_rn(i1c, wv);           // i1 + 0 exact when no event

            // deferred outputs for step k-1: y_new == [v2, i2, s2] in all cases
            size_t ob = ((size_t)(k - 1) * NN + n) * 3;
            ys[ob + 0] = v;
            ys[ob + 1] = i2km1;
            ys[ob + 2] = s;
            if (eventp && cnt < MAXS) {
                size_t eb = ((size_t)cnt * NN + n) * 3;
                yev[eb + 0] = v1s;                // pre-transition y at event step
                yev[eb + 1] = i1c;
                yev[eb + 2] = s1s;
                et[(size_t)cnt * NN + n] = maskp ? 1.0f : 0.0f;
                if (n == 0) tev[cnt] = __fmul_rn((float)k, dt);  // ((k-1)+1)*dt
                cnt++;
            }
        }

        if (k < TT) {
            // ---- advance to end-of-step-k state ----
            float t1  = __fsub_rn(__fadd_rn(i2km1, ick), v);          // (i + ic) - v
            float v1  = __fadd_rn(v, __fmul_rn(dt, __fmul_rn(mu1, t1)));
            float i1n = __fadd_rn(i2km1, __fmul_rn(dt, __fmul_rn(nmu2, i2km1)));
            float v2  = mask ? __fsub_rn(v1, 1.0f) : v1;
            float s2  = mask ? __fsub_rn(logf(uk), ALPHA_F) : s1;

            v1s = v1; s1s = s1; maskp = mask;
            v = v2; i1c = i1n; s = s2;
        }
    }

    if (n == 0) nsp[0] = (float)cnt;
}

extern "C" void kernel_launch(void* const* d_in, const int* in_sizes, int n_in,
                              void* d_out, int out_size) {
    const float* w  = (const float*)d_in[0];
    const float* mu = (const float*)d_in[1];
    const float* v0 = (const float*)d_in[2];
    const float* i0 = (const float*)d_in[3];
    const float* ic = (const float*)d_in[4];
    const float* u0 = (const float*)d_in[5];
    const float* ur = (const float*)d_in[6];
    float* out = (float*)d_out;

    init_kernel<<<512, 256>>>(out);
    sim_kernel<<<G_CTAS, 32>>>(w, mu, v0, i0, ic, u0, ur, out);
    (void)in_sizes; (void)n_in; (void)out_size;
}

// round 6
// speedup vs baseline: 2.4220x; 1.1213x over previous
#include <cuda_runtime.h>
#include <cstdint>

#define NN 2048
#define TT 4096
#define MAXS 256
#define C_CTAS 8
#define NPC 256            /* neurons (=threads) per CTA */
#define WARPS 8            /* warps per CTA */
#define NSLOTS 64          /* total publishing warps in cluster */
#define DEPTH 8            /* slot ring depth (skew bound is 2) */
#define DT 2.44140625e-4f  /* (1-0)/4096, exact in fp32 */
#define ALPHA_F 0.01f

__global__ void init_kernel(float* __restrict__ out) {
    int idx = blockIdx.x * blockDim.x + threadIdx.x;
    int stride = gridDim.x * blockDim.x;
    // Output layout: [ys (T*N*3)] [tev (256)] [yev (256*N*3)] [et (256*N)] [num_spikes (1)]
    float* tev = out + (size_t)TT * NN * 3;
    const int inf_n = MAXS + MAXS * NN * 3;          // tevents + yevents -> +inf
    const float finf = __int_as_float(0x7f800000);
    for (int t = idx; t < inf_n; t += stride) tev[t] = finf;
    float* et = tev + inf_n;
    const int et_n = MAXS * NN;                      // event_types -> 0
    for (int t = idx; t < et_n; t += stride) et[t] = 0.0f;
}

__device__ __forceinline__ unsigned ld_vol_shared(unsigned addr) {
    unsigned v;
    asm volatile("ld.volatile.shared.u32 %0, [%1];" : "=r"(v) : "r"(addr));
    return v;
}
__device__ __forceinline__ void st_shared_cluster(unsigned addr, unsigned v) {
    asm volatile("st.shared::cluster.u32 [%0], %1;" :: "r"(addr), "r"(v) : "memory");
}
__device__ __forceinline__ unsigned mapa_u32(unsigned addr, unsigned rank) {
    unsigned r;
    asm("mapa.shared::cluster.u32 %0, %1, %2;" : "=r"(r) : "r"(addr), "r"(rank));
    return r;
}
__device__ __forceinline__ unsigned smem_u32(const void* p) {
    unsigned a;
    asm("{ .reg .u64 t; cvta.to.shared.u64 t, %1; cvt.u32.u64 %0, t; }" : "=r"(a) : "l"(p));
    return a;
}

// Exact jax.nn.softplus(x) = max(x,0) + log1p(exp(-|x|))
__device__ __forceinline__ float softplus_ref(float v) {
    float ax = fabsf(v);
    float e  = expf(-ax);
    float l  = log1pf(e);
    return __fadd_rn(fmaxf(v, 0.0f), l);
}

__global__ void __launch_bounds__(NPC, 1) __cluster_dims__(C_CTAS, 1, 1)
sim_kernel(const float* __restrict__ w,  const float* __restrict__ mu,
           const float* __restrict__ v0, const float* __restrict__ i0,
           const float* __restrict__ ic, const float* __restrict__ u0,
           const float* __restrict__ ur, float* __restrict__ out)
{
    __shared__ unsigned slots[DEPTH * NSLOTS];   // [ring][64 warp slots], tagged values

    const int t    = threadIdx.x;
    const int lane = t & 31;
    const int wid  = t >> 5;
    const int cta  = blockIdx.x;                 // grid == one cluster -> rank
    const int n    = cta * NPC + t;

    const float mu1  = mu[0];
    const float nmu2 = -mu[1];
    const float dt   = DT;

    float* ys  = out;
    float* tev = out + (size_t)TT * NN * 3;
    float* yev = tev + MAXS;
    float* et  = yev + (size_t)MAXS * NN * 3;
    float* nsp = et  + (size_t)MAXS * NN;

    // zero the slot ring, then cluster-sync before anyone publishes
    for (int i = t; i < DEPTH * NSLOTS; i += NPC) slots[i] = 0u;
    const unsigned sbase = smem_u32(slots);
    unsigned peer[C_CTAS];
    #pragma unroll
    for (int r = 0; r < C_CTAS; ++r) peer[r] = mapa_u32(sbase, (unsigned)r);
    asm volatile("barrier.cluster.arrive.aligned;" ::: "memory");
    asm volatile("barrier.cluster.wait.aligned;"   ::: "memory");

    // Carried state (end of step k-1):
    float v   = v0[n];                              // v2(k-1)
    float s   = __fsub_rn(logf(u0[n]), ALPHA_F);    // s2(k-1)
    float i1c = 0.0f;                               // i1(k-1), BEFORE w-row (k>=1)
    const float i0v = i0[n];
    float v1s = 0.0f, s1s = 0.0f;                   // saved v1(k-1), s1(k-1)
    bool  maskp = false;
    int   cnt = 0;

    for (int k = 0; k <= TT; ++k) {
        // inputs for step k — issued early, consumed in advance at the bottom
        float ick = 0.0f, uk = 0.0f;
        if (k < TT) {
            ick = __ldg(&ic[(size_t)k * NN + n]);
            uk  = __ldg(&ur[(size_t)k * NN + n]);
        }

        // ---- resolve step k-1: poll LOCAL smem slots, then issue w gather ----
        bool  eventp = false;
        float wv = 0.0f;
        if (k > 0) {
            const int kk = k - 1;
            const unsigned want = (unsigned)(kk + 1) << 12;
            const unsigned boff = sbase + (unsigned)((kk & (DEPTH - 1)) * NSLOTS) * 4u;
            unsigned a, b;
            do {
                a = ld_vol_shared(boff + lane * 4u);
                b = ld_vol_shared(boff + (lane + 32) * 4u);
            } while (__ballot_sync(0xffffffffu,
                     (((a ^ want) | (b ^ want)) & 0xFFFFF000u) != 0u));
            unsigned m = __reduce_min_sync(0xffffffffu, umin(a, b));
            unsigned code = m & 0xFFFu;
            eventp = (code != 0xFFFu);
            if (eventp)                                  // LDG in flight under publish
                wv = __ldg(&w[(size_t)(code - 1u) * NN + n]);
        }

        // ---- publish step k (needs only v2(k-1), s2(k-1); overlaps the w LDG) ----
        float s1 = 0.0f;
        bool  mask = false;
        if (k < TT) {
            float sp = softplus_ref(v);
            s1   = __fadd_rn(s, __fmul_rn(dt, sp));
            mask = (s1 >= 0.0f);
            unsigned bal = __ballot_sync(0xffffffffu, mask);
            // code = first spiking global index + 1 (ffs is 1-based), or 0xFFF
            unsigned code = bal ? (unsigned)(cta * NPC + wid * 32) + (unsigned)__ffs(bal)
                                : 0xFFFu;
            unsigned val = ((unsigned)(k + 1) << 12) | code;
            if (lane == 0) {
                unsigned off = (unsigned)(((k & (DEPTH - 1)) * NSLOTS + cta * WARPS + wid)) * 4u;
                #pragma unroll
                for (int r = 0; r < C_CTAS; ++r)
                    st_shared_cluster(peer[r] + off, val);
            }
        }

        // ---- finish step k-1: i2, deferred outputs ----
        float i2km1;
        if (k == 0) {
            i2km1 = i0v;
        } else {
            i2km1 = __fadd_rn(i1c, wv);              // +0 exact when no event
            size_t ob = ((size_t)(k - 1) * NN + n) * 3;
            ys[ob + 0] = v;
            ys[ob + 1] = i2km1;
            ys[ob + 2] = s;
            if (eventp && cnt < MAXS) {
                size_t eb = ((size_t)cnt * NN + n) * 3;
                yev[eb + 0] = v1s;                   // pre-transition y at event step
                yev[eb + 1] = i1c;
                yev[eb + 2] = s1s;
                et[(size_t)cnt * NN + n] = maskp ? 1.0f : 0.0f;
                if (n == 0) tev[cnt] = __fmul_rn((float)k, dt);  // ((k-1)+1)*dt
                cnt++;
            }
        }

        // ---- advance to end-of-step-k state ----
        if (k < TT) {
            float t1  = __fsub_rn(__fadd_rn(i2km1, ick), v);          // (i + ic) - v
            float v1  = __fadd_rn(v, __fmul_rn(dt, __fmul_rn(mu1, t1)));
            float i1n = __fadd_rn(i2km1, __fmul_rn(dt, __fmul_rn(nmu2, i2km1)));
            float v2  = mask ? __fsub_rn(v1, 1.0f) : v1;
            float s2  = mask ? __fsub_rn(logf(uk), ALPHA_F) : s1;

            v1s = v1; s1s = s1; maskp = mask;
            v = v2; i1c = i1n; s = s2;
        }
    }

    if (n == 0) nsp[0] = (float)cnt;

    // no CTA may exit while peers could still address its SMEM
    asm volatile("barrier.cluster.arrive.aligned;" ::: "memory");
    asm volatile("barrier.cluster.wait.aligned;"   ::: "memory");
}

extern "C" void kernel_launch(void* const* d_in, const int* in_sizes, int n_in,
                              void* d_out, int out_size) {
    const float* w  = (const float*)d_in[0];
    const float* mu = (const float*)d_in[1];
    const float* v0 = (const float*)d_in[2];
    const float* i0 = (const float*)d_in[3];
    const float* ic = (const float*)d_in[4];
    const float* u0 = (const float*)d_in[5];
    const float* ur = (const float*)d_in[6];
    float* out = (float*)d_out;

    init_kernel<<<512, 256>>>(out);
    sim_kernel<<<C_CTAS, NPC>>>(w, mu, v0, i0, ic, u0, ur, out);
    (void)in_sizes; (void)n_in; (void)out_size;
}

// round 7
// speedup vs baseline: 4.0911x; 1.6891x over previous
#include <cuda_runtime.h>
#include <cstdint>

#define NN 2048
#define TT 4096
#define MAXS 256
#define C_CTAS 8
#define NPC 256            /* neurons (=threads) per CTA */
#define WARPS 8            /* warps per CTA */
#define NSLOTS 64          /* total publishing warps in cluster */
#define DEPTH 8            /* slot ring depth (skew bound is 2) */
#define PF 4               /* ic/ur prefetch depth (register ring) */
#define DT 2.44140625e-4f  /* (1-0)/4096, exact in fp32 */
#define ALPHA_F 0.01f

__global__ void init_kernel(float* __restrict__ out) {
    int idx = blockIdx.x * blockDim.x + threadIdx.x;
    int stride = gridDim.x * blockDim.x;
    // Output layout: [ys (T*N*3)] [tev (256)] [yev (256*N*3)] [et (256*N)] [num_spikes (1)]
    float* tev = out + (size_t)TT * NN * 3;
    const int inf_n = MAXS + MAXS * NN * 3;          // tevents + yevents -> +inf
    const float finf = __int_as_float(0x7f800000);
    for (int t = idx; t < inf_n; t += stride) tev[t] = finf;
    float* et = tev + inf_n;
    const int et_n = MAXS * NN;                      // event_types -> 0
    for (int t = idx; t < et_n; t += stride) et[t] = 0.0f;
}

__device__ __forceinline__ unsigned ld_vol_shared(unsigned addr) {
    unsigned v;
    asm volatile("ld.volatile.shared.u32 %0, [%1];" : "=r"(v) : "r"(addr));
    return v;
}
__device__ __forceinline__ void st_shared_cluster(unsigned addr, unsigned v) {
    asm volatile("st.shared::cluster.u32 [%0], %1;" :: "r"(addr), "r"(v) : "memory");
}
__device__ __forceinline__ unsigned mapa_u32(unsigned addr, unsigned rank) {
    unsigned r;
    asm("mapa.shared::cluster.u32 %0, %1, %2;" : "=r"(r) : "r"(addr), "r"(rank));
    return r;
}
__device__ __forceinline__ unsigned smem_u32(const void* p) {
    unsigned a;
    asm("{ .reg .u64 t; cvta.to.shared.u64 t, %1; cvt.u32.u64 %0, t; }" : "=r"(a) : "l"(p));
    return a;
}

// Exact jax.nn.softplus(x) = max(x,0) + log1p(exp(-|x|))
__device__ __forceinline__ float softplus_ref(float v) {
    float ax = fabsf(v);
    float e  = expf(-ax);
    float l  = log1pf(e);
    return __fadd_rn(fmaxf(v, 0.0f), l);
}

__global__ void __launch_bounds__(NPC, 1) __cluster_dims__(C_CTAS, 1, 1)
sim_kernel(const float* __restrict__ w,  const float* __restrict__ mu,
           const float* __restrict__ v0, const float* __restrict__ i0,
           const float* __restrict__ ic, const float* __restrict__ u0,
           const float* __restrict__ ur, float* __restrict__ out)
{
    __shared__ unsigned slots[DEPTH * NSLOTS];   // [ring][64 warp slots], tagged values

    const int t    = threadIdx.x;
    const int lane = t & 31;
    const int wid  = t >> 5;
    const int cta  = blockIdx.x;                 // grid == one cluster -> rank
    const int n    = cta * NPC + t;

    const float mu1  = mu[0];
    const float nmu2 = -mu[1];
    const float dt   = DT;

    float* ys  = out;
    float* tev = out + (size_t)TT * NN * 3;
    float* yev = tev + MAXS;
    float* et  = yev + (size_t)MAXS * NN * 3;
    float* nsp = et  + (size_t)MAXS * NN;

    // zero the slot ring, then cluster-sync before anyone publishes
    for (int i = t; i < DEPTH * NSLOTS; i += NPC) slots[i] = 0u;
    const unsigned sbase = smem_u32(slots);
    // each of lanes 0..7 injects the publish into one peer CTA
    const unsigned my_peer = mapa_u32(sbase, (unsigned)(lane & 7));
    const unsigned my_slot_off = (unsigned)(cta * WARPS + wid) * 4u;
    asm volatile("barrier.cluster.arrive.aligned;" ::: "memory");
    asm volatile("barrier.cluster.wait.aligned;"   ::: "memory");

    // Carried state (end of step k-1):
    float v   = v0[n];                              // v2(k-1)
    float s   = __fsub_rn(logf(u0[n]), ALPHA_F);    // s2(k-1)
    float i1c = 0.0f;                               // i1(k-1), BEFORE w-row (k>=1)
    const float i0v = i0[n];
    float v1s = 0.0f, s1s = 0.0f;                   // saved v1(k-1), s1(k-1)
    bool  maskp = false;
    int   cnt = 0;

    // prefetch ring: ic/u for steps 0..PF-1
    float icb[PF], ub[PF];
    #pragma unroll
    for (int j = 0; j < PF; ++j) {
        icb[j] = __ldg(&ic[(size_t)j * NN + n]);
        ub[j]  = __ldg(&ur[(size_t)j * NN + n]);
    }

    // ---------------- peeled k = 0 (no resolve: i2 = i0) ----------------
    {
        float sp = softplus_ref(v);
        float s1 = __fadd_rn(s, __fmul_rn(dt, sp));
        bool  mask = (s1 >= 0.0f);
        unsigned bal  = __ballot_sync(0xffffffffu, mask);
        unsigned code = bal ? (unsigned)(cta * NPC + wid * 32) + (unsigned)__ffs(bal)
                            : 0xFFFu;
        unsigned val = (1u << 12) | code;
        if (lane < 8) st_shared_cluster(my_peer + my_slot_off, val);

        float lu  = __fsub_rn(logf(ub[0]), ALPHA_F);
        float ick = icb[0];
        icb[0] = __ldg(&ic[(size_t)PF * NN + n]);
        ub[0]  = __ldg(&ur[(size_t)PF * NN + n]);

        float t1  = __fsub_rn(__fadd_rn(i0v, ick), v);
        float v1  = __fadd_rn(v, __fmul_rn(dt, __fmul_rn(mu1, t1)));
        float i1n = __fadd_rn(i0v, __fmul_rn(dt, __fmul_rn(nmu2, i0v)));
        float v2  = mask ? __fsub_rn(v1, 1.0f) : v1;
        float s2  = mask ? lu : s1;
        v1s = v1; s1s = s1; maskp = mask;
        v = v2; i1c = i1n; s = s2;
    }

    // ---------------- main loop k = 1 .. TT-1 ----------------
    #pragma unroll 4
    for (int k = 1; k < TT; ++k) {
        const int p = k & (PF - 1);

        // ---- publish step k FIRST (needs only carried v, s) ----
        float sp = softplus_ref(v);
        float s1 = __fadd_rn(s, __fmul_rn(dt, sp));
        bool  mask = (s1 >= 0.0f);
        unsigned bal  = __ballot_sync(0xffffffffu, mask);
        unsigned code = bal ? (unsigned)(cta * NPC + wid * 32) + (unsigned)__ffs(bal)
                            : 0xFFFu;
        unsigned val = ((unsigned)(k + 1) << 12) | code;
        if (lane < 8)
            st_shared_cluster(my_peer + (unsigned)((k & (DEPTH - 1)) * NSLOTS) * 4u
                                      + my_slot_off, val);

        // ---- off-chain work while peers' publishes propagate ----
        float lu  = __fsub_rn(logf(ub[p]), ALPHA_F);   // u loaded PF steps ago
        float ick = icb[p];
        int   kp  = (k + PF < TT) ? (k + PF) : (TT - 1);
        icb[p] = __ldg(&ic[(size_t)kp * NN + n]);
        ub[p]  = __ldg(&ur[(size_t)kp * NN + n]);

        // ---- resolve step k-1: poll local smem, then w gather ----
        const unsigned want = (unsigned)k << 12;       // tag of step k-1
        const unsigned boff = sbase + (unsigned)(((k - 1) & (DEPTH - 1)) * NSLOTS) * 4u;
        unsigned a, b;
        do {
            a = ld_vol_shared(boff + lane * 4u);
            b = ld_vol_shared(boff + (lane + 32) * 4u);
        } while (__ballot_sync(0xffffffffu,
                 (((a ^ want) | (b ^ want)) & 0xFFFFF000u) != 0u));
        unsigned m = __reduce_min_sync(0xffffffffu, umin(a, b));
        unsigned ecode = m & 0xFFFu;
        bool eventp = (ecode != 0xFFFu);
        float wv = 0.0f;
        if (eventp) wv = __ldg(&w[(size_t)(ecode - 1u) * NN + n]);

        float ysv = v, yss = s, i1old = i1c;
        float i2  = __fadd_rn(i1old, wv);              // +0 exact when no event

        // ---- advance to end-of-step-k state (critical chain) ----
        float t1  = __fsub_rn(__fadd_rn(i2, ick), v);
        float v1  = __fadd_rn(v, __fmul_rn(dt, __fmul_rn(mu1, t1)));
        float i1n = __fadd_rn(i2, __fmul_rn(dt, __fmul_rn(nmu2, i2)));
        float v2  = mask ? __fsub_rn(v1, 1.0f) : v1;
        float s2  = mask ? lu : s1;

        // ---- deferred outputs for step k-1 (fire-and-forget) ----
        size_t ob = ((size_t)(k - 1) * NN + n) * 3;
        ys[ob + 0] = ysv;
        ys[ob + 1] = i2;
        ys[ob + 2] = yss;
        if (eventp && cnt < MAXS) {
            size_t eb = ((size_t)cnt * NN + n) * 3;
            yev[eb + 0] = v1s;                         // pre-transition y at event step
            yev[eb + 1] = i1old;
            yev[eb + 2] = s1s;
            et[(size_t)cnt * NN + n] = maskp ? 1.0f : 0.0f;
            if (n == 0) tev[cnt] = __fmul_rn((float)k, dt);  // ((k-1)+1)*dt
            cnt++;
        }

        v1s = v1; s1s = s1; maskp = mask;
        v = v2; i1c = i1n; s = s2;
    }

    // ---------------- epilogue: resolve step TT-1 ----------------
    {
        const unsigned want = (unsigned)TT << 12;
        const unsigned boff = sbase + (unsigned)(((TT - 1) & (DEPTH - 1)) * NSLOTS) * 4u;
        unsigned a, b;
        do {
            a = ld_vol_shared(boff + lane * 4u);
            b = ld_vol_shared(boff + (lane + 32) * 4u);
        } while (__ballot_sync(0xffffffffu,
                 (((a ^ want) | (b ^ want)) & 0xFFFFF000u) != 0u));
        unsigned m = __reduce_min_sync(0xffffffffu, umin(a, b));
        unsigned ecode = m & 0xFFFu;
        bool eventp = (ecode != 0xFFFu);
        float wv = 0.0f;
        if (eventp) wv = __ldg(&w[(size_t)(ecode - 1u) * NN + n]);
        float i2 = __fadd_rn(i1c, wv);

        size_t ob = ((size_t)(TT - 1) * NN + n) * 3;
        ys[ob + 0] = v;
        ys[ob + 1] = i2;
        ys[ob + 2] = s;
        if (eventp && cnt < MAXS) {
            size_t eb = ((size_t)cnt * NN + n) * 3;
            yev[eb + 0] = v1s;
            yev[eb + 1] = i1c;
            yev[eb + 2] = s1s;
            et[(size_t)cnt * NN + n] = maskp ? 1.0f : 0.0f;
            if (n == 0) tev[cnt] = __fmul_rn((float)TT, dt);
            cnt++;
        }
    }

    if (n == 0) nsp[0] = (float)cnt;

    // no CTA may exit while peers could still address its SMEM
    asm volatile("barrier.cluster.arrive.aligned;" ::: "memory");
    asm volatile("barrier.cluster.wait.aligned;"   ::: "memory");
}

extern "C" void kernel_launch(void* const* d_in, const int* in_sizes, int n_in,
                              void* d_out, int out_size) {
    const float* w  = (const float*)d_in[0];
    const float* mu = (const float*)d_in[1];
    const float* v0 = (const float*)d_in[2];
    const float* i0 = (const float*)d_in[3];
    const float* ic = (const float*)d_in[4];
    const float* u0 = (const float*)d_in[5];
    const float* ur = (const float*)d_in[6];
    float* out = (float*)d_out;

    init_kernel<<<512, 256>>>(out);
    sim_kernel<<<C_CTAS, NPC>>>(w, mu, v0, i0, ic, u0, ur, out);
    (void)in_sizes; (void)n_in; (void)out_size;
}